// round 8
// baseline (speedup 1.0000x reference)
#include <cuda_runtime.h>
#include <cstdint>

// Shapes: N=100000, D=64, H=128, E=1600000
#define Dk     64
#define Hk     128
#define TE     64       // edges per tile
#define UVP    136      // Us/Vs pitch (floats) -> conflict-free f2 fragment loads
#define UVPc   132
#define MAXN   100000

// Scratch: U = nodes @ W1[:64,:] (columns permuted), V = nodes @ W1[64:,:]
__device__ float g_U[(size_t)MAXN * Hk];
__device__ float g_V[(size_t)MAXN * Hk];

// hidden-dim permutation within each 8-group: position s holds unit perm[s]
__device__ __constant__ int c_perm[8] = {0, 4, 1, 5, 2, 6, 3, 7};

// ---------------- smem float-index layout for edge kernel ----------------
#define F_US   0                          // [64][UVP]
#define F_VS   (F_US + TE * UVP)          // [64][UVP]
#define F_EIS  (F_VS + TE * UVP)          // 64 ints
#define F_EJS  (F_EIS + TE)
#define F_TOT  (F_EJS + TE)
#define EDGE_SMEM_BYTES (F_TOT * 4)

extern __shared__ char smem_raw[];

__device__ __forceinline__ uint32_t smem_u32(const void* p) {
    uint32_t a;
    asm("{ .reg .u64 t; cvta.to.shared.u64 t, %1; cvt.u32.u64 %0, t; }" : "=r"(a) : "l"(p));
    return a;
}
__device__ __forceinline__ float to_tf32(float x) {
    float y; asm("cvt.rna.tf32.f32 %0, %1;" : "=f"(y) : "f"(x)); return y;
}
__device__ __forceinline__ void red_add_v2(float* addr, float x, float y) {
    asm volatile("red.global.add.v2.f32 [%0], {%1,%2};"
                 :: "l"(addr), "f"(x), "f"(y) : "memory");
}
__device__ __forceinline__ void cp_async16(void* sdst, const void* gsrc) {
    uint32_t s = smem_u32(sdst);
    asm volatile("cp.async.cg.shared.global [%0], [%1], 16;" :: "r"(s), "l"(gsrc) : "memory");
}
__device__ __forceinline__ void mma_tf32(float c[4],
                                         uint32_t a0, uint32_t a1, uint32_t a2, uint32_t a3,
                                         uint32_t b0, uint32_t b1) {
    asm volatile(
        "mma.sync.aligned.m16n8k8.row.col.f32.tf32.tf32.f32 "
        "{%0,%1,%2,%3}, {%4,%5,%6,%7}, {%8,%9}, {%0,%1,%2,%3};"
        : "+f"(c[0]), "+f"(c[1]), "+f"(c[2]), "+f"(c[3])
        : "r"(a0), "r"(a1), "r"(a2), "r"(a3), "r"(b0), "r"(b1));
}

// ---------------- Kernel 0: out = nodes ----------------
__global__ __launch_bounds__(256) void copy_kernel(const float* __restrict__ nodes,
                                                   float* __restrict__ out, int n4) {
    int i = blockIdx.x * blockDim.x + threadIdx.x;
    if (i < n4) ((float4*)out)[i] = ((const float4*)nodes)[i];
}

// ---------------- Kernel A: U/V precompute (fp32 SIMT, permuted columns) ----
__global__ __launch_bounds__(256) void uv_kernel(const float* __restrict__ nodes,
                                                 const float* __restrict__ W1, int N) {
    float* smem = (float*)smem_raw;
    float* Ns  = smem;                // [64][UVPc]
    float* W1s = smem + 64 * UVPc;    // [128][128] (columns permuted)

    int tid = threadIdx.x;
    for (int idx = tid; idx < 128 * 128; idx += 256) {
        int c = idx & 127;
        int src_c = (c & ~7) + c_perm[c & 7];
        W1s[idx] = W1[(idx & ~127) + src_c];
    }

    int n_base = blockIdx.x * 128;
    for (int idx = tid; idx < 128 * 64; idx += 256) {
        int k = idx & 63, n = idx >> 6;
        int gn = n_base + n;
        Ns[k * UVPc + n] = (gn < N) ? nodes[gn * Dk + k] : 0.f;
    }
    __syncthreads();

    int ty = tid >> 4, tx = tid & 15;
    int n0 = ty * 8, c0 = tx * 8;

    #pragma unroll
    for (int pass = 0; pass < 2; pass++) {
        const float* Wb = W1s + pass * 64 * 128;
        float acc[8][8];
        #pragma unroll
        for (int a = 0; a < 8; a++)
            #pragma unroll
            for (int b = 0; b < 8; b++) acc[a][b] = 0.f;

        #pragma unroll 4
        for (int k = 0; k < 64; k++) {
            float4 a0 = *(const float4*)&Ns[k * UVPc + n0];
            float4 a1 = *(const float4*)&Ns[k * UVPc + n0 + 4];
            float4 w0 = *(const float4*)&Wb[k * 128 + c0];
            float4 w1 = *(const float4*)&Wb[k * 128 + c0 + 4];
            float af[8] = {a0.x, a0.y, a0.z, a0.w, a1.x, a1.y, a1.z, a1.w};
            float wf[8] = {w0.x, w0.y, w0.z, w0.w, w1.x, w1.y, w1.z, w1.w};
            #pragma unroll
            for (int a = 0; a < 8; a++)
                #pragma unroll
                for (int b = 0; b < 8; b++) acc[a][b] += af[a] * wf[b];
        }

        float* Out = pass ? g_V : g_U;
        #pragma unroll
        for (int a = 0; a < 8; a++) {
            int gn = n_base + n0 + a;
            if (gn < N) {
                *(float4*)&Out[(size_t)gn * Hk + c0] =
                    make_float4(acc[a][0], acc[a][1], acc[a][2], acc[a][3]);
                *(float4*)&Out[(size_t)gn * Hk + c0 + 4] =
                    make_float4(acc[a][4], acc[a][5], acc[a][6], acc[a][7]);
            }
        }
    }
}

// ---------------- Kernel B: persistent edge kernel ----------
// Warp tiling (8 warps): mt(2, m32) x nh(2, n32) x kh(2, k64).
// W2 B-fragments and b1 fragments are REGISTER-RESIDENT (loaded once from gmem).
// Partial-K sums from the two kh warps combine via the atomic scatter.
// Per 64-edge tile, per direction:
//   cp.async-stage raw rows US = U[sn[e]], VS = V[on[e]]
//   A-fragments on the fly: a = tf32(relu(us + vs + b1))
//   C_partial = H[:, kh*64:kh*64+64] @ W2[kh*64:...,:]  (m16n8k8 tf32 mma)
//   out[sn] += C_partial (+ b2 via acc-init on kh=0)    (red.global.add.v2)
__global__ __launch_bounds__(256, 2) void edge_kernel(const int* __restrict__ edges,
                                                      const float* __restrict__ W2,
                                                      const float* __restrict__ b1,
                                                      const float* __restrict__ b2,
                                                      float* __restrict__ out,
                                                      int E, int tiles) {
    float* smem = (float*)smem_raw;
    float* US  = smem + F_US;
    float* VS  = smem + F_VS;
    int*   eis = (int*)(smem + F_EIS);
    int*   ejs = (int*)(smem + F_EJS);

    int tid = threadIdx.x, wid = tid >> 5, lane = tid & 31;
    int rr = lane >> 2, q = lane & 3;

    int mt = wid & 1;            // m32 tile
    int nh = (wid >> 1) & 1;     // n32 half
    int kh = (wid >> 2) & 1;     // k64 half
    int er0 = mt * 32;
    int n0  = nh * 32;
    int kc0 = kh * 64;

    // ---- one-time register staging (from gmem; amortized over whole kernel) ----
    // B-frag: bfr[g][j] = {tf32(W2[unit(col)][n]), tf32(W2[unit(col+1)][n])}
    //   col = kc0 + g*8 + 2q (permuted index), n = n0 + 8j + rr
    uint32_t bfr[8][4][2];
    float2 b1r[8];
    #pragma unroll
    for (int g = 0; g < 8; g++) {
        int col = kc0 + g * 8 + 2 * q;
        int u0 = (col & ~7) + c_perm[col & 7];
        int u1 = ((col + 1) & ~7) + c_perm[(col + 1) & 7];
        b1r[g] = make_float2(b1[u0], b1[u1]);
        #pragma unroll
        for (int j = 0; j < 4; j++) {
            int n = n0 + 8 * j + rr;
            bfr[g][j][0] = __float_as_uint(to_tf32(W2[u0 * Dk + n]));
            bfr[g][j][1] = __float_as_uint(to_tf32(W2[u1 * Dk + n]));
        }
    }
    // b2 fragment: only kh==0 warps seed it (avoid double count)
    float2 b2r[4];
    #pragma unroll
    for (int j = 0; j < 4; j++) {
        int nb = n0 + 8 * j + 2 * q;
        b2r[j] = (kh == 0) ? make_float2(b2[nb], b2[nb + 1]) : make_float2(0.f, 0.f);
    }

    for (int t = blockIdx.x; t < tiles; t += gridDim.x) {
        int ebase = t * TE;
        if (tid < TE) {
            int e = ebase + tid;
            int a = 0, b = 0;
            if (e < E) { a = edges[2 * e]; b = edges[2 * e + 1]; }
            eis[tid] = a; ejs[tid] = b;
        }
        __syncthreads();

        #pragma unroll
        for (int dir = 0; dir < 2; dir++) {
            const int* sn = dir ? ejs : eis;    // U-index + scatter target
            const int* on = dir ? eis : ejs;    // V-index

            // ---- stage raw U/V rows via cp.async (512B per row) ----
            {
                int r = wid * 8;
                #pragma unroll
                for (int k = 0; k < 8; k++) {
                    const float* up = g_U + (size_t)sn[r + k] * Hk;
                    const float* vp = g_V + (size_t)on[r + k] * Hk;
                    cp_async16(&US[(r + k) * UVP + lane * 4], up + lane * 4);
                    cp_async16(&VS[(r + k) * UVP + lane * 4], vp + lane * 4);
                }
            }
            asm volatile("cp.async.commit_group;" ::: "memory");
            asm volatile("cp.async.wait_group 0;" ::: "memory");
            __syncthreads();

            // ---- MMA with fused layer-1; B from registers ----
            float acc[2][4][4];
            #pragma unroll
            for (int mm = 0; mm < 2; mm++)
                #pragma unroll
                for (int j = 0; j < 4; j++) {
                    acc[mm][j][0] = b2r[j].x; acc[mm][j][1] = b2r[j].y;
                    acc[mm][j][2] = b2r[j].x; acc[mm][j][3] = b2r[j].y;
                }

            #pragma unroll
            for (int g = 0; g < 8; g++) {
                int col = kc0 + g * 8 + 2 * q;
                float2 bb = b1r[g];
                uint32_t a[2][4];
                #pragma unroll
                for (int mm = 0; mm < 2; mm++) {
                    int rbase = er0 + 16 * mm + rr;
                    float2 u0 = *(const float2*)&US[rbase * UVP + col];
                    float2 v0 = *(const float2*)&VS[rbase * UVP + col];
                    float2 u1 = *(const float2*)&US[(rbase + 8) * UVP + col];
                    float2 v1 = *(const float2*)&VS[(rbase + 8) * UVP + col];
                    a[mm][0] = __float_as_uint(to_tf32(fmaxf(u0.x + v0.x + bb.x, 0.f)));
                    a[mm][2] = __float_as_uint(to_tf32(fmaxf(u0.y + v0.y + bb.y, 0.f)));
                    a[mm][1] = __float_as_uint(to_tf32(fmaxf(u1.x + v1.x + bb.x, 0.f)));
                    a[mm][3] = __float_as_uint(to_tf32(fmaxf(u1.y + v1.y + bb.y, 0.f)));
                }
                #pragma unroll
                for (int j = 0; j < 4; j++) {
                    #pragma unroll
                    for (int mm = 0; mm < 2; mm++)
                        mma_tf32(acc[mm][j], a[mm][0], a[mm][1], a[mm][2], a[mm][3],
                                 bfr[g][j][0], bfr[g][j][1]);
                }
            }

            // ---- scatter (both kh warps RED partial sums; b2 seeded on kh=0 only) ----
            #pragma unroll
            for (int mm = 0; mm < 2; mm++) {
                #pragma unroll
                for (int half = 0; half < 2; half++) {
                    int er = er0 + 16 * mm + rr + 8 * half;
                    if (ebase + er < E) {
                        int node = sn[er];
                        float* base = out + (size_t)node * Dk;
                        #pragma unroll
                        for (int j = 0; j < 4; j++) {
                            int nb = n0 + 8 * j + 2 * q;
                            red_add_v2(base + nb, acc[mm][j][2 * half + 0],
                                                  acc[mm][j][2 * half + 1]);
                        }
                    }
                }
            }
            __syncthreads();   // US/VS free for next dir
        }
    }
}

extern "C" void kernel_launch(void* const* d_in, const int* in_sizes, int n_in,
                              void* d_out, int out_size) {
    const float* nodes = (const float*)d_in[0];
    const int*   edges = (const int*)d_in[1];
    const float* W1    = (const float*)d_in[2];
    const float* b1    = (const float*)d_in[3];
    const float* W2    = (const float*)d_in[4];
    const float* b2    = (const float*)d_in[5];
    float* out = (float*)d_out;

    int N = in_sizes[0] / Dk;
    int E = in_sizes[1] / 2;

    static int nsm = 0;
    const int uv_smem = (64 * UVPc + 128 * 128) * 4;
    if (!nsm) {
        cudaDeviceGetAttribute(&nsm, cudaDevAttrMultiProcessorCount, 0);
        cudaFuncSetAttribute(uv_kernel,   cudaFuncAttributeMaxDynamicSharedMemorySize, uv_smem);
        cudaFuncSetAttribute(edge_kernel, cudaFuncAttributeMaxDynamicSharedMemorySize, EDGE_SMEM_BYTES);
    }

    int n4 = (N * Dk) / 4;
    copy_kernel<<<(n4 + 255) / 256, 256>>>(nodes, out, n4);

    int uv_blocks = (N + 127) / 128;
    uv_kernel<<<uv_blocks, 256, uv_smem>>>(nodes, W1, N);

    int tiles = (E + TE - 1) / TE;
    edge_kernel<<<2 * nsm, 256, EDGE_SMEM_BYTES>>>(edges, W2, b1, b2, out, E, tiles);
}

// round 9
// speedup vs baseline: 1.1438x; 1.1438x over previous
#include <cuda_runtime.h>
#include <cstdint>

// Shapes: N=100000, D=64, H=128, E=1600000
#define Dk     64
#define Hk     128
#define TE     64       // edges per tile
#define UVP    136      // Us/Vs pitch (floats)
#define W2P    136
#define UVPc   132
#define MAXN   100000

// Scratch: U = nodes @ W1[:64,:] (columns permuted), V = nodes @ W1[64:,:]
__device__ float g_U[(size_t)MAXN * Hk];
__device__ float g_V[(size_t)MAXN * Hk];

// hidden-dim permutation within each 8-group: position s holds unit perm[s]
__device__ __constant__ int c_perm[8] = {0, 4, 1, 5, 2, 6, 3, 7};

// ---------------- smem float-index layout for edge kernel ----------------
#define F_US   0                          // [64][UVP]
#define F_VS   (F_US + TE * UVP)          // [64][UVP]
#define F_W2   (F_VS + TE * UVP)          // [64][W2P]
#define F_B1   (F_W2 + Dk * W2P)          // 128 (permuted)
#define F_B2   (F_B1 + Hk)                // 64
#define F_EIS  (F_B2 + Dk)                // 64 ints
#define F_EJS  (F_EIS + TE)
#define F_TOT  (F_EJS + TE)
#define EDGE_SMEM_BYTES (F_TOT * 4)

extern __shared__ char smem_raw[];

__device__ __forceinline__ uint32_t smem_u32(const void* p) {
    uint32_t a;
    asm("{ .reg .u64 t; cvta.to.shared.u64 t, %1; cvt.u32.u64 %0, t; }" : "=r"(a) : "l"(p));
    return a;
}
__device__ __forceinline__ float to_tf32(float x) {
    float y; asm("cvt.rna.tf32.f32 %0, %1;" : "=f"(y) : "f"(x)); return y;
}
__device__ __forceinline__ void red_add_v4(float* addr, float x, float y, float z, float w) {
    asm volatile("red.global.add.v4.f32 [%0], {%1,%2,%3,%4};"
                 :: "l"(addr), "f"(x), "f"(y), "f"(z), "f"(w) : "memory");
}
__device__ __forceinline__ void cp_async16(void* sdst, const void* gsrc) {
    uint32_t s = smem_u32(sdst);
    asm volatile("cp.async.cg.shared.global [%0], [%1], 16;" :: "r"(s), "l"(gsrc) : "memory");
}
__device__ __forceinline__ void mma_tf32(float c[4],
                                         uint32_t a0, uint32_t a1, uint32_t a2, uint32_t a3,
                                         uint32_t b0, uint32_t b1) {
    asm volatile(
        "mma.sync.aligned.m16n8k8.row.col.f32.tf32.tf32.f32 "
        "{%0,%1,%2,%3}, {%4,%5,%6,%7}, {%8,%9}, {%0,%1,%2,%3};"
        : "+f"(c[0]), "+f"(c[1]), "+f"(c[2]), "+f"(c[3])
        : "r"(a0), "r"(a1), "r"(a2), "r"(a3), "r"(b0), "r"(b1));
}

// ---------------- Kernel 0: out = nodes ----------------
__global__ __launch_bounds__(256) void copy_kernel(const float* __restrict__ nodes,
                                                   float* __restrict__ out, int n4) {
    int i = blockIdx.x * blockDim.x + threadIdx.x;
    if (i < n4) ((float4*)out)[i] = ((const float4*)nodes)[i];
}

// ---------------- Kernel A: U/V precompute (fp32 SIMT, permuted columns) ----
__global__ __launch_bounds__(256) void uv_kernel(const float* __restrict__ nodes,
                                                 const float* __restrict__ W1, int N) {
    float* smem = (float*)smem_raw;
    float* Ns  = smem;                // [64][UVPc]
    float* W1s = smem + 64 * UVPc;    // [128][128] (columns permuted)

    int tid = threadIdx.x;
    for (int idx = tid; idx < 128 * 128; idx += 256) {
        int c = idx & 127;
        int src_c = (c & ~7) + c_perm[c & 7];
        W1s[idx] = W1[(idx & ~127) + src_c];
    }

    int n_base = blockIdx.x * 128;
    for (int idx = tid; idx < 128 * 64; idx += 256) {
        int k = idx & 63, n = idx >> 6;
        int gn = n_base + n;
        Ns[k * UVPc + n] = (gn < N) ? nodes[gn * Dk + k] : 0.f;
    }
    __syncthreads();

    int ty = tid >> 4, tx = tid & 15;
    int n0 = ty * 8, c0 = tx * 8;

    #pragma unroll
    for (int pass = 0; pass < 2; pass++) {
        const float* Wb = W1s + pass * 64 * 128;
        float acc[8][8];
        #pragma unroll
        for (int a = 0; a < 8; a++)
            #pragma unroll
            for (int b = 0; b < 8; b++) acc[a][b] = 0.f;

        #pragma unroll 4
        for (int k = 0; k < 64; k++) {
            float4 a0 = *(const float4*)&Ns[k * UVPc + n0];
            float4 a1 = *(const float4*)&Ns[k * UVPc + n0 + 4];
            float4 w0 = *(const float4*)&Wb[k * 128 + c0];
            float4 w1 = *(const float4*)&Wb[k * 128 + c0 + 4];
            float af[8] = {a0.x, a0.y, a0.z, a0.w, a1.x, a1.y, a1.z, a1.w};
            float wf[8] = {w0.x, w0.y, w0.z, w0.w, w1.x, w1.y, w1.z, w1.w};
            #pragma unroll
            for (int a = 0; a < 8; a++)
                #pragma unroll
                for (int b = 0; b < 8; b++) acc[a][b] += af[a] * wf[b];
        }

        float* Out = pass ? g_V : g_U;
        #pragma unroll
        for (int a = 0; a < 8; a++) {
            int gn = n_base + n0 + a;
            if (gn < N) {
                *(float4*)&Out[(size_t)gn * Hk + c0] =
                    make_float4(acc[a][0], acc[a][1], acc[a][2], acc[a][3]);
                *(float4*)&Out[(size_t)gn * Hk + c0 + 4] =
                    make_float4(acc[a][4], acc[a][5], acc[a][6], acc[a][7]);
            }
        }
    }
}

// ---------------- Kernel B: persistent edge kernel (R6 + v4 shfl REDs) ----
// Per 64-edge tile, per direction:
//   cp.async-stage raw rows US = U[sn[e]], VS = V[on[e]]
//   A-fragments on the fly: a = tf32(relu(us + vs + b1))
//   C = H @ W2 via m16n8k8 tf32 mma  (warp = m16 x n32)
//   scatter: fold b2, shfl-pair adjacent lanes into 16B payloads,
//            out[sn] += C via red.global.add.v4  (half the RED warp-ops)
__global__ __launch_bounds__(256, 2) void edge_kernel(const int* __restrict__ edges,
                                                      const float* __restrict__ W2,
                                                      const float* __restrict__ b1,
                                                      const float* __restrict__ b2,
                                                      float* __restrict__ out,
                                                      int E, int tiles) {
    float* smem = (float*)smem_raw;
    float* US  = smem + F_US;
    float* VS  = smem + F_VS;
    float* W2S = smem + F_W2;
    float* b1s = smem + F_B1;
    float* b2s = smem + F_B2;
    int*   eis = (int*)(smem + F_EIS);
    int*   ejs = (int*)(smem + F_EJS);

    int tid = threadIdx.x, wid = tid >> 5, lane = tid & 31;
    int rr = lane >> 2, q = lane & 3;
    int s = q & 1, tq = q >> 1;

    // ---- one-time staging ----
    // W2S[n][k'] = tf32(W2[unit(k')][n])
    for (int idx = tid; idx < Hk * Dk; idx += 256) {
        int k = idx >> 6, n = idx & 63;
        int unit = (k & ~7) + c_perm[k & 7];
        W2S[n * W2P + k] = to_tf32(W2[unit * Dk + n]);
    }
    if (tid < Hk) b1s[tid] = b1[(tid & ~7) + c_perm[tid & 7]];
    if (tid < Dk) b2s[tid] = b2[tid];
    __syncthreads();

    // warp tiling: 4 m16-tiles x 2 n-halves
    int mt = wid & 3;
    int er0 = mt * 16;
    int n0 = (wid >> 2) * 32;

    for (int t = blockIdx.x; t < tiles; t += gridDim.x) {
        int ebase = t * TE;
        if (tid < TE) {
            int e = ebase + tid;
            int a = 0, b = 0;
            if (e < E) { a = edges[2 * e]; b = edges[2 * e + 1]; }
            eis[tid] = a; ejs[tid] = b;
        }
        __syncthreads();

        #pragma unroll
        for (int dir = 0; dir < 2; dir++) {
            const int* sn = dir ? ejs : eis;    // U-index + scatter target
            const int* on = dir ? eis : ejs;    // V-index

            // ---- stage raw U/V rows via cp.async (512B per row) ----
            #pragma unroll
            for (int r = wid; r < TE; r += 8) {
                const float* up = g_U + (size_t)sn[r] * Hk;
                const float* vp = g_V + (size_t)on[r] * Hk;
                cp_async16(&US[r * UVP + lane * 4], up + lane * 4);
                cp_async16(&VS[r * UVP + lane * 4], vp + lane * 4);
            }
            asm volatile("cp.async.commit_group;" ::: "memory");
            asm volatile("cp.async.wait_group 0;" ::: "memory");
            __syncthreads();

            // ---- MMA with fused layer-1 in A-fragment loads ----
            float acc[4][4];
            #pragma unroll
            for (int j = 0; j < 4; j++)
                #pragma unroll
                for (int x = 0; x < 4; x++) acc[j][x] = 0.f;

            #pragma unroll 4
            for (int g = 0; g < 16; g++) {
                int col = g * 8 + 2 * q;
                float2 bb = *(const float2*)&b1s[col];
                float2 u0 = *(const float2*)&US[(er0 + rr) * UVP + col];
                float2 v0 = *(const float2*)&VS[(er0 + rr) * UVP + col];
                float2 u1 = *(const float2*)&US[(er0 + rr + 8) * UVP + col];
                float2 v1 = *(const float2*)&VS[(er0 + rr + 8) * UVP + col];
                uint32_t a0 = __float_as_uint(to_tf32(fmaxf(u0.x + v0.x + bb.x, 0.f)));
                uint32_t a2 = __float_as_uint(to_tf32(fmaxf(u0.y + v0.y + bb.y, 0.f)));
                uint32_t a1 = __float_as_uint(to_tf32(fmaxf(u1.x + v1.x + bb.x, 0.f)));
                uint32_t a3 = __float_as_uint(to_tf32(fmaxf(u1.y + v1.y + bb.y, 0.f)));
                #pragma unroll
                for (int j = 0; j < 4; j++) {
                    float2 bf = *(const float2*)&W2S[(n0 + 8 * j + rr) * W2P + col];
                    mma_tf32(acc[j], a0, a1, a2, a3,
                             __float_as_uint(bf.x), __float_as_uint(bf.y));
                }
            }

            // ---- scatter: fold b2, shfl-pair, red.v4 ----
            {
                // fold b2 into all fragment elements
                #pragma unroll
                for (int j = 0; j < 4; j++) {
                    int nb = n0 + 8 * j + 2 * q;
                    float bx = b2s[nb], by = b2s[nb + 1];
                    acc[j][0] += bx; acc[j][1] += by;
                    acc[j][2] += bx; acc[j][3] += by;
                }
                // even lanes (s=0) emit row er; odd lanes (s=1) emit row er+8
                int er = er0 + rr + 8 * s;
                bool valid = (ebase + er) < E;
                int node = valid ? sn[er] : 0;
                float* base = out + (size_t)node * Dk;
                #pragma unroll
                for (int j = 0; j < 4; j++) {
                    float y0 = __shfl_xor_sync(0xffffffffu, s ? acc[j][0] : acc[j][2], 1);
                    float y1 = __shfl_xor_sync(0xffffffffu, s ? acc[j][1] : acc[j][3], 1);
                    float p0 = s ? y0 : acc[j][0];
                    float p1 = s ? y1 : acc[j][1];
                    float p2 = s ? acc[j][2] : y0;
                    float p3 = s ? acc[j][3] : y1;
                    if (valid) {
                        int nb = n0 + 8 * j + 4 * tq;
                        red_add_v4(base + nb, p0, p1, p2, p3);
                    }
                }
            }
            __syncthreads();   // US/VS free for next dir
        }
    }
}

extern "C" void kernel_launch(void* const* d_in, const int* in_sizes, int n_in,
                              void* d_out, int out_size) {
    const float* nodes = (const float*)d_in[0];
    const int*   edges = (const int*)d_in[1];
    const float* W1    = (const float*)d_in[2];
    const float* b1    = (const float*)d_in[3];
    const float* W2    = (const float*)d_in[4];
    const float* b2    = (const float*)d_in[5];
    float* out = (float*)d_out;

    int N = in_sizes[0] / Dk;
    int E = in_sizes[1] / 2;

    static int nsm = 0;
    const int uv_smem = (64 * UVPc + 128 * 128) * 4;
    if (!nsm) {
        cudaDeviceGetAttribute(&nsm, cudaDevAttrMultiProcessorCount, 0);
        cudaFuncSetAttribute(uv_kernel,   cudaFuncAttributeMaxDynamicSharedMemorySize, uv_smem);
        cudaFuncSetAttribute(edge_kernel, cudaFuncAttributeMaxDynamicSharedMemorySize, EDGE_SMEM_BYTES);
    }

    int n4 = (N * Dk) / 4;
    copy_kernel<<<(n4 + 255) / 256, 256>>>(nodes, out, n4);

    int uv_blocks = (N + 127) / 128;
    uv_kernel<<<uv_blocks, 256, uv_smem>>>(nodes, W1, N);

    int tiles = (E + TE - 1) / TE;
    edge_kernel<<<2 * nsm, 256, EDGE_SMEM_BYTES>>>(edges, W2, b1, b2, out, E, tiles);
}

// round 10
// speedup vs baseline: 1.2125x; 1.0601x over previous
#include <cuda_runtime.h>
#include <cstdint>

// Shapes: N=100000, D=64, H=128, E=1600000
#define Dk     64
#define Hk     128
#define TE     64       // edges per tile
#define UVP    136      // Us/Vs pitch (floats)
#define W2P    136
#define UVPc   132
#define MAXN   100000

// Scratch: U = nodes @ W1[:64,:] (columns permuted), V = nodes @ W1[64:,:]
__device__ float g_U[(size_t)MAXN * Hk];
__device__ float g_V[(size_t)MAXN * Hk];

// hidden-dim permutation within each 8-group: position s holds unit perm[s]
__device__ __constant__ int c_perm[8] = {0, 4, 1, 5, 2, 6, 3, 7};

// ---------------- smem float-index layout for edge kernel ----------------
#define F_US   0                          // [64][UVP]; also reused as kh-partial scratch
#define F_VS   (F_US + TE * UVP)          // [64][UVP]
#define F_W2   (F_VS + TE * UVP)          // [64][W2P]
#define F_B1   (F_W2 + Dk * W2P)          // 128 (permuted)
#define F_B2   (F_B1 + Hk)                // 64
#define F_EIS  (F_B2 + Dk)                // 64 ints
#define F_EJS  (F_EIS + TE)
#define F_TOT  (F_EJS + TE)
#define EDGE_SMEM_BYTES (F_TOT * 4)

extern __shared__ char smem_raw[];

__device__ __forceinline__ uint32_t smem_u32(const void* p) {
    uint32_t a;
    asm("{ .reg .u64 t; cvta.to.shared.u64 t, %1; cvt.u32.u64 %0, t; }" : "=r"(a) : "l"(p));
    return a;
}
__device__ __forceinline__ float to_tf32(float x) {
    float y; asm("cvt.rna.tf32.f32 %0, %1;" : "=f"(y) : "f"(x)); return y;
}
__device__ __forceinline__ void red_add_v4(float* addr, float x, float y, float z, float w) {
    asm volatile("red.global.add.v4.f32 [%0], {%1,%2,%3,%4};"
                 :: "l"(addr), "f"(x), "f"(y), "f"(z), "f"(w) : "memory");
}
__device__ __forceinline__ void cp_async16(void* sdst, const void* gsrc) {
    uint32_t s = smem_u32(sdst);
    asm volatile("cp.async.cg.shared.global [%0], [%1], 16;" :: "r"(s), "l"(gsrc) : "memory");
}
__device__ __forceinline__ void mma_tf32(float c[4],
                                         uint32_t a0, uint32_t a1, uint32_t a2, uint32_t a3,
                                         uint32_t b0, uint32_t b1) {
    asm volatile(
        "mma.sync.aligned.m16n8k8.row.col.f32.tf32.tf32.f32 "
        "{%0,%1,%2,%3}, {%4,%5,%6,%7}, {%8,%9}, {%0,%1,%2,%3};"
        : "+f"(c[0]), "+f"(c[1]), "+f"(c[2]), "+f"(c[3])
        : "r"(a0), "r"(a1), "r"(a2), "r"(a3), "r"(b0), "r"(b1));
}

// ---------------- Kernel 0: out = nodes ----------------
__global__ __launch_bounds__(256) void copy_kernel(const float* __restrict__ nodes,
                                                   float* __restrict__ out, int n4) {
    int i = blockIdx.x * blockDim.x + threadIdx.x;
    if (i < n4) ((float4*)out)[i] = ((const float4*)nodes)[i];
}

// ---------------- Kernel A: U/V precompute (fp32 SIMT, permuted columns) ----
__global__ __launch_bounds__(256) void uv_kernel(const float* __restrict__ nodes,
                                                 const float* __restrict__ W1, int N) {
    float* smem = (float*)smem_raw;
    float* Ns  = smem;                // [64][UVPc]
    float* W1s = smem + 64 * UVPc;    // [128][128] (columns permuted)

    int tid = threadIdx.x;
    for (int idx = tid; idx < 128 * 128; idx += 256) {
        int c = idx & 127;
        int src_c = (c & ~7) + c_perm[c & 7];
        W1s[idx] = W1[(idx & ~127) + src_c];
    }

    int n_base = blockIdx.x * 128;
    for (int idx = tid; idx < 128 * 64; idx += 256) {
        int k = idx & 63, n = idx >> 6;
        int gn = n_base + n;
        Ns[k * UVPc + n] = (gn < N) ? nodes[gn * Dk + k] : 0.f;
    }
    __syncthreads();

    int ty = tid >> 4, tx = tid & 15;
    int n0 = ty * 8, c0 = tx * 8;

    #pragma unroll
    for (int pass = 0; pass < 2; pass++) {
        const float* Wb = W1s + pass * 64 * 128;
        float acc[8][8];
        #pragma unroll
        for (int a = 0; a < 8; a++)
            #pragma unroll
            for (int b = 0; b < 8; b++) acc[a][b] = 0.f;

        #pragma unroll 4
        for (int k = 0; k < 64; k++) {
            float4 a0 = *(const float4*)&Ns[k * UVPc + n0];
            float4 a1 = *(const float4*)&Ns[k * UVPc + n0 + 4];
            float4 w0 = *(const float4*)&Wb[k * 128 + c0];
            float4 w1 = *(const float4*)&Wb[k * 128 + c0 + 4];
            float af[8] = {a0.x, a0.y, a0.z, a0.w, a1.x, a1.y, a1.z, a1.w};
            float wf[8] = {w0.x, w0.y, w0.z, w0.w, w1.x, w1.y, w1.z, w1.w};
            #pragma unroll
            for (int a = 0; a < 8; a++)
                #pragma unroll
                for (int b = 0; b < 8; b++) acc[a][b] += af[a] * wf[b];
        }

        float* Out = pass ? g_V : g_U;
        #pragma unroll
        for (int a = 0; a < 8; a++) {
            int gn = n_base + n0 + a;
            if (gn < N) {
                *(float4*)&Out[(size_t)gn * Hk + c0] =
                    make_float4(acc[a][0], acc[a][1], acc[a][2], acc[a][3]);
                *(float4*)&Out[(size_t)gn * Hk + c0 + 4] =
                    make_float4(acc[a][4], acc[a][5], acc[a][6], acc[a][7]);
            }
        }
    }
}

// ---------------- Kernel B: persistent edge kernel ----------
// Warp tiling (8 warps): mt(2, m32) x nh(2, n32) x kh(2, k64); B from smem.
// Per 64-edge tile, per direction:
//   cp.async-stage raw rows US = U[sn[e]], VS = V[on[e]]
//   A-fragments on the fly: a = tf32(relu(us + vs + b1))
//   each kh-warp computes a K=64 partial of C = H @ W2 (m16n8k8 mma)
//   kh=1 partials stored to smem scratch; kh=0 warps add, fold b2,
//   shfl-pair into 16B payloads, out[sn] += C via red.global.add.v4
__global__ __launch_bounds__(256, 2) void edge_kernel(const int* __restrict__ edges,
                                                      const float* __restrict__ W2,
                                                      const float* __restrict__ b1,
                                                      const float* __restrict__ b2,
                                                      float* __restrict__ out,
                                                      int E, int tiles) {
    float* smem = (float*)smem_raw;
    float* US  = smem + F_US;
    float* VS  = smem + F_VS;
    float* W2S = smem + F_W2;
    float* b1s = smem + F_B1;
    float* b2s = smem + F_B2;
    float* SCR = smem + F_US;          // kh-partial scratch (16KB), reuses US
    int*   eis = (int*)(smem + F_EIS);
    int*   ejs = (int*)(smem + F_EJS);

    int tid = threadIdx.x, wid = tid >> 5, lane = tid & 31;
    int rr = lane >> 2, q = lane & 3;
    int s = q & 1, tq = q >> 1;

    int kh = wid >> 2;           // k64 half
    int wq = wid & 3;            // quadrant id (shared between kh pair)
    int er0 = (wq & 1) * 32;     // m32 tile
    int n0  = (wq >> 1) * 32;    // n32 half
    int kc0 = kh * 64;

    // ---- one-time staging ----
    // W2S[n][k'] = tf32(W2[unit(k')][n])
    for (int idx = tid; idx < Hk * Dk; idx += 256) {
        int k = idx >> 6, n = idx & 63;
        int unit = (k & ~7) + c_perm[k & 7];
        W2S[n * W2P + k] = to_tf32(W2[unit * Dk + n]);
    }
    if (tid < Hk) b1s[tid] = b1[(tid & ~7) + c_perm[tid & 7]];
    if (tid < Dk) b2s[tid] = b2[tid];
    __syncthreads();

    for (int t = blockIdx.x; t < tiles; t += gridDim.x) {
        int ebase = t * TE;
        if (tid < TE) {
            int e = ebase + tid;
            int a = 0, b = 0;
            if (e < E) { a = edges[2 * e]; b = edges[2 * e + 1]; }
            eis[tid] = a; ejs[tid] = b;
        }
        __syncthreads();

        #pragma unroll
        for (int dir = 0; dir < 2; dir++) {
            const int* sn = dir ? ejs : eis;    // U-index + scatter target
            const int* on = dir ? eis : ejs;    // V-index

            // ---- stage raw U/V rows via cp.async (512B per row) ----
            #pragma unroll
            for (int r = wid; r < TE; r += 8) {
                const float* up = g_U + (size_t)sn[r] * Hk;
                const float* vp = g_V + (size_t)on[r] * Hk;
                cp_async16(&US[r * UVP + lane * 4], up + lane * 4);
                cp_async16(&VS[r * UVP + lane * 4], vp + lane * 4);
            }
            asm volatile("cp.async.commit_group;" ::: "memory");
            asm volatile("cp.async.wait_group 0;" ::: "memory");
            __syncthreads();

            // ---- K=64 partial MMA with fused layer-1 ----
            float acc[2][4][4];
            #pragma unroll
            for (int mm = 0; mm < 2; mm++)
                #pragma unroll
                for (int j = 0; j < 4; j++)
                    #pragma unroll
                    for (int x = 0; x < 4; x++) acc[mm][j][x] = 0.f;

            #pragma unroll
            for (int g = 0; g < 8; g++) {
                int col = kc0 + g * 8 + 2 * q;
                float2 bb = *(const float2*)&b1s[col];
                uint32_t a[2][4];
                #pragma unroll
                for (int mm = 0; mm < 2; mm++) {
                    int rbase = er0 + 16 * mm + rr;
                    float2 u0 = *(const float2*)&US[rbase * UVP + col];
                    float2 v0 = *(const float2*)&VS[rbase * UVP + col];
                    float2 u1 = *(const float2*)&US[(rbase + 8) * UVP + col];
                    float2 v1 = *(const float2*)&VS[(rbase + 8) * UVP + col];
                    a[mm][0] = __float_as_uint(to_tf32(fmaxf(u0.x + v0.x + bb.x, 0.f)));
                    a[mm][2] = __float_as_uint(to_tf32(fmaxf(u0.y + v0.y + bb.y, 0.f)));
                    a[mm][1] = __float_as_uint(to_tf32(fmaxf(u1.x + v1.x + bb.x, 0.f)));
                    a[mm][3] = __float_as_uint(to_tf32(fmaxf(u1.y + v1.y + bb.y, 0.f)));
                }
                #pragma unroll
                for (int j = 0; j < 4; j++) {
                    float2 bf = *(const float2*)&W2S[(n0 + 8 * j + rr) * W2P + col];
                    uint32_t bu0 = __float_as_uint(bf.x);
                    uint32_t bu1 = __float_as_uint(bf.y);
                    #pragma unroll
                    for (int mm = 0; mm < 2; mm++)
                        mma_tf32(acc[mm][j], a[mm][0], a[mm][1], a[mm][2], a[mm][3], bu0, bu1);
                }
            }
            __syncthreads();   // US reads done; SCR (=US) safe to write

            // ---- kh=1 warps publish partials (idx-major, conflict-free f4) ----
            float* af = &acc[0][0][0];
            if (kh == 1) {
                #pragma unroll
                for (int idx = 0; idx < 8; idx++) {
                    *(float4*)&SCR[((idx * 4 + wq) * 32 + lane) * 4] =
                        make_float4(af[idx * 4], af[idx * 4 + 1],
                                    af[idx * 4 + 2], af[idx * 4 + 3]);
                }
            }
            __syncthreads();

            // ---- kh=0 warps: combine, fold b2, shfl-pair, red.v4 ----
            if (kh == 0) {
                #pragma unroll
                for (int idx = 0; idx < 8; idx++) {
                    float4 p = *(const float4*)&SCR[((idx * 4 + wq) * 32 + lane) * 4];
                    af[idx * 4]     += p.x;
                    af[idx * 4 + 1] += p.y;
                    af[idx * 4 + 2] += p.z;
                    af[idx * 4 + 3] += p.w;
                }
                #pragma unroll
                for (int j = 0; j < 4; j++) {
                    int nb = n0 + 8 * j + 2 * q;
                    float bx = b2s[nb], by = b2s[nb + 1];
                    #pragma unroll
                    for (int mm = 0; mm < 2; mm++) {
                        acc[mm][j][0] += bx; acc[mm][j][1] += by;
                        acc[mm][j][2] += bx; acc[mm][j][3] += by;
                    }
                }
                #pragma unroll
                for (int mm = 0; mm < 2; mm++) {
                    int er = er0 + 16 * mm + rr + 8 * s;
                    bool valid = (ebase + er) < E;
                    int node = valid ? sn[er] : 0;
                    float* base = out + (size_t)node * Dk;
                    #pragma unroll
                    for (int j = 0; j < 4; j++) {
                        float y0 = __shfl_xor_sync(0xffffffffu,
                                       s ? acc[mm][j][0] : acc[mm][j][2], 1);
                        float y1 = __shfl_xor_sync(0xffffffffu,
                                       s ? acc[mm][j][1] : acc[mm][j][3], 1);
                        float p0 = s ? y0 : acc[mm][j][0];
                        float p1 = s ? y1 : acc[mm][j][1];
                        float p2 = s ? acc[mm][j][2] : y0;
                        float p3 = s ? acc[mm][j][3] : y1;
                        if (valid) {
                            int nb = n0 + 8 * j + 4 * tq;
                            red_add_v4(base + nb, p0, p1, p2, p3);
                        }
                    }
                }
            }
            __syncthreads();   // SCR/US free for next dir restaging
        }
    }
}

extern "C" void kernel_launch(void* const* d_in, const int* in_sizes, int n_in,
                              void* d_out, int out_size) {
    const float* nodes = (const float*)d_in[0];
    const int*   edges = (const int*)d_in[1];
    const float* W1    = (const float*)d_in[2];
    const float* b1    = (const float*)d_in[3];
    const float* W2    = (const float*)d_in[4];
    const float* b2    = (const float*)d_in[5];
    float* out = (float*)d_out;

    int N = in_sizes[0] / Dk;
    int E = in_sizes[1] / 2;

    static int nsm = 0;
    const int uv_smem = (64 * UVPc + 128 * 128) * 4;
    if (!nsm) {
        cudaDeviceGetAttribute(&nsm, cudaDevAttrMultiProcessorCount, 0);
        cudaFuncSetAttribute(uv_kernel,   cudaFuncAttributeMaxDynamicSharedMemorySize, uv_smem);
        cudaFuncSetAttribute(edge_kernel, cudaFuncAttributeMaxDynamicSharedMemorySize, EDGE_SMEM_BYTES);
    }

    int n4 = (N * Dk) / 4;
    copy_kernel<<<(n4 + 255) / 256, 256>>>(nodes, out, n4);

    int uv_blocks = (N + 127) / 128;
    uv_kernel<<<uv_blocks, 256, uv_smem>>>(nodes, W1, N);

    int tiles = (E + TE - 1) / TE;
    edge_kernel<<<2 * nsm, 256, EDGE_SMEM_BYTES>>>(edges, W2, b1, b2, out, E, tiles);
}

// round 11
// speedup vs baseline: 2.0003x; 1.6498x over previous
#include <cuda_runtime.h>
#include <cuda_fp16.h>
#include <cstdint>

// Shapes: N=100000, D=64, H=128, E=1600000
#define Dk     64
#define Hk     128
#define TE     128      // edges per tile
#define PH     144      // US/VS/W2S pitch in halves (conflict-free LDS.64)
#define UVPc   132
#define MAXN   100000

// Scratch: U = nodes @ W1[:64,:], V = nodes @ W1[64:,:]  (fp16, k-permuted)
__device__ __half g_U[(size_t)MAXN * Hk];
__device__ __half g_V[(size_t)MAXN * Hk];

// per-16-group k permutation: stored position p holds original unit (p&~15)+c_p16[p&15]
// -> lane q's fragment quad {2q,2q+1,2q+8,2q+9} sits at stored positions 4q..4q+3
__device__ __constant__ int c_p16[16] = {0,1,8,9, 2,3,10,11, 4,5,12,13, 6,7,14,15};

// ---------------- smem BYTE layout for edge kernel ----------------
#define B_US   0                          // half[128*PH] = 36864B
#define B_VS   (B_US + TE * PH * 2)       // half[128*PH]
#define B_W2   (B_VS + TE * PH * 2)       // half[64*PH]  = 18432B
#define B_B2   (B_W2 + Dk * PH * 2)       // float[64]
#define B_EIS  (B_B2 + Dk * 4)            // int[128]
#define B_EJS  (B_EIS + TE * 4)           // int[128]
#define EDGE_SMEM_BYTES (B_EJS + TE * 4)

extern __shared__ char smem_raw[];

__device__ __forceinline__ uint32_t smem_u32(const void* p) {
    uint32_t a;
    asm("{ .reg .u64 t; cvta.to.shared.u64 t, %1; cvt.u32.u64 %0, t; }" : "=r"(a) : "l"(p));
    return a;
}
__device__ __forceinline__ void red_add_v4(float* addr, float x, float y, float z, float w) {
    asm volatile("red.global.add.v4.f32 [%0], {%1,%2,%3,%4};"
                 :: "l"(addr), "f"(x), "f"(y), "f"(z), "f"(w) : "memory");
}
__device__ __forceinline__ void cp_async16(void* sdst, const void* gsrc) {
    uint32_t s = smem_u32(sdst);
    asm volatile("cp.async.cg.shared.global [%0], [%1], 16;" :: "r"(s), "l"(gsrc) : "memory");
}
__device__ __forceinline__ void mma_f16(float c[4],
                                        uint32_t a0, uint32_t a1, uint32_t a2, uint32_t a3,
                                        uint32_t b0, uint32_t b1) {
    asm volatile(
        "mma.sync.aligned.m16n8k16.row.col.f32.f16.f16.f32 "
        "{%0,%1,%2,%3}, {%4,%5,%6,%7}, {%8,%9}, {%0,%1,%2,%3};"
        : "+f"(c[0]), "+f"(c[1]), "+f"(c[2]), "+f"(c[3])
        : "r"(a0), "r"(a1), "r"(a2), "r"(a3), "r"(b0), "r"(b1));
}
__device__ __forceinline__ uint32_t relu2add(uint32_t u, uint32_t v, __half2 b) {
    __half2 x = __hadd2(__hadd2(*(__half2*)&u, *(__half2*)&v), b);
    __half2 z = __float2half2_rn(0.f);
    __half2 r = __hmax2(x, z);
    return *(uint32_t*)&r;
}

// ---------------- Kernel 0: out = nodes ----------------
__global__ __launch_bounds__(256) void copy_kernel(const float* __restrict__ nodes,
                                                   float* __restrict__ out, int n4) {
    int i = blockIdx.x * blockDim.x + threadIdx.x;
    if (i < n4) ((float4*)out)[i] = ((const float4*)nodes)[i];
}

// ---------------- Kernel A: U/V precompute -> fp16 permuted ----------------
__global__ __launch_bounds__(256) void uv_kernel(const float* __restrict__ nodes,
                                                 const float* __restrict__ W1, int N) {
    float* smem = (float*)smem_raw;
    float* Ns  = smem;                // [64][UVPc]
    float* W1s = smem + 64 * UVPc;    // [128][128] columns k-permuted

    int tid = threadIdx.x;
    for (int idx = tid; idx < 128 * 128; idx += 256) {
        int c = idx & 127;
        int src_c = (c & ~15) + c_p16[c & 15];
        W1s[idx] = W1[(idx & ~127) + src_c];
    }

    int n_base = blockIdx.x * 128;
    for (int idx = tid; idx < 128 * 64; idx += 256) {
        int k = idx & 63, n = idx >> 6;
        int gn = n_base + n;
        Ns[k * UVPc + n] = (gn < N) ? nodes[gn * Dk + k] : 0.f;
    }
    __syncthreads();

    int ty = tid >> 4, tx = tid & 15;
    int n0 = ty * 8, c0 = tx * 8;

    #pragma unroll
    for (int pass = 0; pass < 2; pass++) {
        const float* Wb = W1s + pass * 64 * 128;
        float acc[8][8];
        #pragma unroll
        for (int a = 0; a < 8; a++)
            #pragma unroll
            for (int b = 0; b < 8; b++) acc[a][b] = 0.f;

        #pragma unroll 4
        for (int k = 0; k < 64; k++) {
            float4 a0 = *(const float4*)&Ns[k * UVPc + n0];
            float4 a1 = *(const float4*)&Ns[k * UVPc + n0 + 4];
            float4 w0 = *(const float4*)&Wb[k * 128 + c0];
            float4 w1 = *(const float4*)&Wb[k * 128 + c0 + 4];
            float af[8] = {a0.x, a0.y, a0.z, a0.w, a1.x, a1.y, a1.z, a1.w};
            float wf[8] = {w0.x, w0.y, w0.z, w0.w, w1.x, w1.y, w1.z, w1.w};
            #pragma unroll
            for (int a = 0; a < 8; a++)
                #pragma unroll
                for (int b = 0; b < 8; b++) acc[a][b] += af[a] * wf[b];
        }

        __half* Out = pass ? g_V : g_U;
        #pragma unroll
        for (int a = 0; a < 8; a++) {
            int gn = n_base + n0 + a;
            if (gn < N) {
                __half2 h01 = __floats2half2_rn(acc[a][0], acc[a][1]);
                __half2 h23 = __floats2half2_rn(acc[a][2], acc[a][3]);
                __half2 h45 = __floats2half2_rn(acc[a][4], acc[a][5]);
                __half2 h67 = __floats2half2_rn(acc[a][6], acc[a][7]);
                uint4 pk;
                pk.x = *(uint32_t*)&h01; pk.y = *(uint32_t*)&h23;
                pk.z = *(uint32_t*)&h45; pk.w = *(uint32_t*)&h67;
                *(uint4*)&Out[(size_t)gn * Hk + c0] = pk;
            }
        }
    }
}

// ---------------- Kernel B: persistent edge kernel, fp16 mma ----------
// Per 128-edge tile, per direction:
//   cp.async-stage fp16 rows US = U[sn[e]], VS = V[on[e]]  (256B/row)
//   A-fragments on the fly: a = HMAX2(HADD2(u, v) + b1, 0)   (all fp16x2)
//   C = H @ W2 via m16n8k16 f16 mma, f32 accum (warp = m32 x n32)
//   scatter: fold b2, shfl-pair, out[sn] += C via red.global.add.v4
__global__ __launch_bounds__(256, 2) void edge_kernel(const int* __restrict__ edges,
                                                      const float* __restrict__ W2,
                                                      const float* __restrict__ b1,
                                                      const float* __restrict__ b2,
                                                      float* __restrict__ out,
                                                      int E, int tiles) {
    char* smem = smem_raw;
    __half* USh = (__half*)(smem + B_US);
    __half* VSh = (__half*)(smem + B_VS);
    __half* W2h = (__half*)(smem + B_W2);
    float*  b2s = (float*)(smem + B_B2);
    int*    eis = (int*)(smem + B_EIS);
    int*    ejs = (int*)(smem + B_EJS);

    int tid = threadIdx.x, wid = tid >> 5, lane = tid & 31;
    int rr = lane >> 2, q = lane & 3;
    int s = q & 1, tq = q >> 1;

    // ---- one-time staging ----
    // W2h[n*PH + kpos] = half(W2[orig(kpos)][n])
    for (int idx = tid; idx < Hk * Dk; idx += 256) {
        int k = idx >> 6, n = idx & 63;
        int unit = (k & ~15) + c_p16[k & 15];
        W2h[n * PH + k] = __float2half(W2[unit * Dk + n]);
    }
    if (tid < Dk) b2s[tid] = b2[tid];

    // register-resident b1 fragment pairs (original indexing)
    __half2 b1lo[8], b1hi[8];
    #pragma unroll
    for (int g = 0; g < 8; g++) {
        b1lo[g] = __floats2half2_rn(b1[g * 16 + 2 * q],     b1[g * 16 + 2 * q + 1]);
        b1hi[g] = __floats2half2_rn(b1[g * 16 + 2 * q + 8], b1[g * 16 + 2 * q + 9]);
    }
    __syncthreads();

    // warp tiling: 4 m32-tiles x 2 n-halves
    int er0 = (wid & 3) * 32;
    int n0  = (wid >> 2) * 32;

    int l16 = lane & 15, h16 = lane >> 4;

    for (int t = blockIdx.x; t < tiles; t += gridDim.x) {
        int ebase = t * TE;
        if (tid < TE) {
            int e = ebase + tid;
            int a = 0, b = 0;
            if (e < E) { a = edges[2 * e]; b = edges[2 * e + 1]; }
            eis[tid] = a; ejs[tid] = b;
        }
        __syncthreads();

        #pragma unroll
        for (int dir = 0; dir < 2; dir++) {
            const int* sn = dir ? ejs : eis;    // U-index + scatter target
            const int* on = dir ? eis : ejs;    // V-index

            // ---- stage fp16 rows via cp.async: 2 rows/warp/iter, 16B per lane ----
            #pragma unroll
            for (int r0 = wid * 16; r0 < wid * 16 + 16; r0 += 2) {
                int row = r0 + h16;
                const __half* up = g_U + (size_t)sn[row] * Hk;
                const __half* vp = g_V + (size_t)on[row] * Hk;
                cp_async16(USh + row * PH + l16 * 8, up + l16 * 8);
                cp_async16(VSh + row * PH + l16 * 8, vp + l16 * 8);
            }
            asm volatile("cp.async.commit_group;" ::: "memory");
            asm volatile("cp.async.wait_group 0;" ::: "memory");
            __syncthreads();

            // ---- MMA: 8 k16-steps, fused fp16 layer-1 ----
            float acc[2][4][4];
            #pragma unroll
            for (int mm = 0; mm < 2; mm++)
                #pragma unroll
                for (int j = 0; j < 4; j++)
                    #pragma unroll
                    for (int x = 0; x < 4; x++) acc[mm][j][x] = 0.f;

            #pragma unroll
            for (int g = 0; g < 8; g++) {
                int kof = g * 16 + 4 * q;
                uint32_t a[2][4];
                #pragma unroll
                for (int mm = 0; mm < 2; mm++) {
                    int base = (er0 + 16 * mm + rr) * PH + kof;
                    uint2 u0 = *(const uint2*)(USh + base);
                    uint2 v0 = *(const uint2*)(VSh + base);
                    uint2 u1 = *(const uint2*)(USh + base + 8 * PH);
                    uint2 v1 = *(const uint2*)(VSh + base + 8 * PH);
                    a[mm][0] = relu2add(u0.x, v0.x, b1lo[g]);
                    a[mm][2] = relu2add(u0.y, v0.y, b1hi[g]);
                    a[mm][1] = relu2add(u1.x, v1.x, b1lo[g]);
                    a[mm][3] = relu2add(u1.y, v1.y, b1hi[g]);
                }
                #pragma unroll
                for (int j = 0; j < 4; j++) {
                    uint2 bb = *(const uint2*)(W2h + (n0 + 8 * j + rr) * PH + kof);
                    #pragma unroll
                    for (int mm = 0; mm < 2; mm++)
                        mma_f16(acc[mm][j], a[mm][0], a[mm][1], a[mm][2], a[mm][3],
                                bb.x, bb.y);
                }
            }

            // ---- scatter: fold b2, shfl-pair, red.v4 ----
            #pragma unroll
            for (int j = 0; j < 4; j++) {
                int nb = n0 + 8 * j + 2 * q;
                float bx = b2s[nb], by = b2s[nb + 1];
                #pragma unroll
                for (int mm = 0; mm < 2; mm++) {
                    acc[mm][j][0] += bx; acc[mm][j][1] += by;
                    acc[mm][j][2] += bx; acc[mm][j][3] += by;
                }
            }
            #pragma unroll
            for (int mm = 0; mm < 2; mm++) {
                int er = er0 + 16 * mm + rr + 8 * s;
                bool valid = (ebase + er) < E;
                int node = valid ? sn[er] : 0;
                float* base = out + (size_t)node * Dk;
                #pragma unroll
                for (int j = 0; j < 4; j++) {
                    float y0 = __shfl_xor_sync(0xffffffffu,
                                   s ? acc[mm][j][0] : acc[mm][j][2], 1);
                    float y1 = __shfl_xor_sync(0xffffffffu,
                                   s ? acc[mm][j][1] : acc[mm][j][3], 1);
                    float p0 = s ? y0 : acc[mm][j][0];
                    float p1 = s ? y1 : acc[mm][j][1];
                    float p2 = s ? acc[mm][j][2] : y0;
                    float p3 = s ? acc[mm][j][3] : y1;
                    if (valid) {
                        int nb = n0 + 8 * j + 4 * tq;
                        red_add_v4(base + nb, p0, p1, p2, p3);
                    }
                }
            }
            __syncthreads();   // US/VS free for next dir
        }
    }
}

extern "C" void kernel_launch(void* const* d_in, const int* in_sizes, int n_in,
                              void* d_out, int out_size) {
    const float* nodes = (const float*)d_in[0];
    const int*   edges = (const int*)d_in[1];
    const float* W1    = (const float*)d_in[2];
    const float* b1    = (const float*)d_in[3];
    const float* W2    = (const float*)d_in[4];
    const float* b2    = (const float*)d_in[5];
    float* out = (float*)d_out;

    int N = in_sizes[0] / Dk;
    int E = in_sizes[1] / 2;

    static int nsm = 0;
    const int uv_smem = (64 * UVPc + 128 * 128) * 4;
    if (!nsm) {
        cudaDeviceGetAttribute(&nsm, cudaDevAttrMultiProcessorCount, 0);
        cudaFuncSetAttribute(uv_kernel,   cudaFuncAttributeMaxDynamicSharedMemorySize, uv_smem);
        cudaFuncSetAttribute(edge_kernel, cudaFuncAttributeMaxDynamicSharedMemorySize, EDGE_SMEM_BYTES);
    }

    int n4 = (N * Dk) / 4;
    copy_kernel<<<(n4 + 255) / 256, 256>>>(nodes, out, n4);

    int uv_blocks = (N + 127) / 128;
    uv_kernel<<<uv_blocks, 256, uv_smem>>>(nodes, W1, N);

    int tiles = (E + TE - 1) / TE;
    edge_kernel<<<2 * nsm, 256, EDGE_SMEM_BYTES>>>(edges, W2, b1, b2, out, E, tiles);
}